// round 14
// baseline (speedup 1.0000x reference)
#include <cuda_runtime.h>
#include <cuda_fp16.h>
#include <cstdint>
#include <math.h>

#define BSZ 8
#define SEQ 1024
#define EMB 1024
#define NH 16
#define HD 64
#define M_TOT (BSZ*SEQ)   // 8192
#define MSZ ((size_t)M_TOT*EMB)
#define WSZ ((size_t)EMB*EMB)

__device__ __half g_w_h[4*WSZ];     // weights hi
__device__ __half g_w_l[4*WSZ];     // weights lo
__device__ __half g_P_hi[3*MSZ];    // projected Q/K/V (fp16)
__device__ __half g_Ch[MSZ];        // attention context (fp16)

__device__ __forceinline__ uint32_t smem_u32(const void* p) {
    uint32_t a;
    asm("{ .reg .u64 t; cvta.to.shared.u64 t, %1; cvt.u32.u64 %0, t; }"
        : "=r"(a) : "l"(p));
    return a;
}

__device__ __forceinline__ void mma16816h(float* c, const uint32_t* a, const uint32_t* b) {
    asm volatile(
        "mma.sync.aligned.m16n8k16.row.col.f32.f16.f16.f32 "
        "{%0,%1,%2,%3}, {%4,%5,%6,%7}, {%8,%9}, {%0,%1,%2,%3};"
        : "+f"(c[0]), "+f"(c[1]), "+f"(c[2]), "+f"(c[3])
        : "r"(a[0]), "r"(a[1]), "r"(a[2]), "r"(a[3]), "r"(b[0]), "r"(b[1]));
}

__device__ __forceinline__ void split2h(float x, float y, uint32_t& hi, uint32_t& lo) {
    __half hx = __float2half_rn(x), hy = __float2half_rn(y);
    float rx = x - __half2float(hx), ry = y - __half2float(hy);
    __half2 hp = {hx, hy};
    __half2 lp = {__float2half_rn(rx), __float2half_rn(ry)};
    hi = *reinterpret_cast<uint32_t*>(&hp);
    lo = *reinterpret_cast<uint32_t*>(&lp);
}
__device__ __forceinline__ uint32_t pack_h2(float x, float y) {
    __half2 p = {__float2half_rn(x), __float2half_rn(y)};
    return *reinterpret_cast<uint32_t*>(&p);
}

// ---------------- weight fp32 -> fp16 hi/lo split (4 tensors) ---------------
struct SplitSrc { const float4* p[4]; };

__global__ __launch_bounds__(256) void split_w(
    SplitSrc s, uint2* __restrict__ wh, uint2* __restrict__ wl)
{
    const int seg = blockIdx.y;
    const int i = blockIdx.x * 256 + threadIdx.x;
    if (i >= (int)(WSZ/4)) return;
    float4 v = s.p[seg][i];
    uint32_t h0, l0, h1, l1;
    split2h(v.x, v.y, h0, l0);
    split2h(v.z, v.w, h1, l1);
    uint2 ho = {h0, h1}, loo = {l0, l1};
    size_t off = (size_t)seg * (WSZ/4) + i;
    wh[off] = ho; wl[off] = loo;
}

// ---------------- common GEMM geometry: 256x128 tile, BK=32 -----------------
#define BK 32
#define NCHUNK (EMB/BK)
#define ROW_B 80
#define TILE_W 10240               // 128 rows x 80B (one W tile)
#define A_TILE 20480               // 256 rows x 80B
#define QKV_SMEM (A_TILE + 4*TILE_W)   // 61440
#define O_STAGE (A_TILE + 2*TILE_W)    // 40960
#define O_SMEM (2*O_STAGE)             // 81920

// ---------------- QKV GEMM: A fp32 (fused convert), W fp16 hi/lo ------------
__global__ __launch_bounds__(256) void gemm_qkv(
    const float* __restrict__ in_q, const float* __restrict__ in_k,
    const float* __restrict__ in_v,
    const __half* __restrict__ Wbase_h, const __half* __restrict__ Wbase_l,
    const float* __restrict__ b0, const float* __restrict__ b1,
    const float* __restrict__ b2, float scale0,
    __half* __restrict__ Pout)
{
    extern __shared__ char smc[];
    const int z = blockIdx.z;
    const int tid = threadIdx.x;
    const int lane = tid & 31, w = tid >> 5;
    const int wy = w >> 2, wx = w & 3;          // 2 x 4 warps; warp tile 128x32
    const int bx = blockIdx.x * 128, by = blockIdx.y * 256;
    const uint32_t sbase = smem_u32(smc);

    const float* A = (z == 0) ? in_q : ((z == 1) ? in_k : in_v);
    const float* Asrc = A + (size_t)by * EMB;
    const __half* Whi = Wbase_h + (size_t)z * WSZ;
    const __half* Wlo = Wbase_l + (size_t)z * WSZ;
    const float* bias = (z == 0) ? b0 : ((z == 1) ? b1 : b2);
    const float scale = (z == 0) ? scale0 : 1.0f;

    const char* wsrc[2] = {
        (const char*)(Whi + (size_t)bx * EMB),
        (const char*)(Wlo + (size_t)bx * EMB)};

    auto prefetchW = [&](int kb, int st) {
#pragma unroll
        for (int t = 0; t < 2; t++)
#pragma unroll
            for (int s = 0; s < 2; s++) {
                int idx = tid + s * 256;
                int r = idx >> 2, c = idx & 3;
                const char* src = wsrc[t] + ((size_t)r * EMB + (size_t)kb * BK) * 2 + c * 16;
                uint32_t dst = sbase + A_TILE + (uint32_t)st * (2*TILE_W)
                             + t * TILE_W + (uint32_t)r * ROW_B + c * 16;
                asm volatile("cp.async.cg.shared.global [%0], [%1], 16;"
                             :: "r"(dst), "l"(src));
            }
        asm volatile("cp.async.commit_group;");
    };

    float4 rA[4][2];     // 256 rows: idx = tid + s*256, s=0..3
    auto ldgA = [&](int kb) {
#pragma unroll
        for (int s = 0; s < 4; s++) {
            int idx = tid + s * 256;
            int r = idx >> 2, c = idx & 3;
            const float* p = Asrc + (size_t)r * EMB + kb * BK + c * 8;
            rA[s][0] = *(const float4*)p;
            rA[s][1] = *(const float4*)(p + 4);
        }
    };
    auto stsA = [&]() {
#pragma unroll
        for (int s = 0; s < 4; s++) {
            int idx = tid + s * 256;
            int r = idx >> 2, c = idx & 3;
            uint4 val;
            val.x = pack_h2(rA[s][0].x, rA[s][0].y);
            val.y = pack_h2(rA[s][0].z, rA[s][0].w);
            val.z = pack_h2(rA[s][1].x, rA[s][1].y);
            val.w = pack_h2(rA[s][1].z, rA[s][1].w);
            *(uint4*)(smc + (uint32_t)r * ROW_B + c * 16) = val;
        }
    };

    float acc[8][4][4];
#pragma unroll
    for (int mi = 0; mi < 8; mi++)
#pragma unroll
        for (int ni = 0; ni < 4; ni++)
#pragma unroll
            for (int j = 0; j < 4; j++) acc[mi][ni][j] = 0.f;

    prefetchW(0, 0);
    ldgA(0);

    for (int kb = 0; kb < NCHUNK; kb++) {
        asm volatile("cp.async.wait_group 0;");
        __syncthreads();          // W(kb) landed; all LDSM of A(kb-1) retired
        stsA();
        __syncthreads();          // A(kb) visible
        if (kb + 1 < NCHUNK) { prefetchW(kb + 1, (kb + 1) & 1); ldgA(kb + 1); }
        const uint32_t wb = sbase + A_TILE + (uint32_t)(kb & 1) * (2*TILE_W);

#pragma unroll
        for (int ks = 0; ks < 2; ks++) {
            uint32_t bh[4][2], bl[4][2];
            const uint32_t brow = wx * 32 + (lane & 7);
            const uint32_t bcol = ks * 16 + ((lane >> 3) & 1) * 8;
#pragma unroll
            for (int ni = 0; ni < 4; ni++) {
                uint32_t ab = wb + (brow + ni * 8) * ROW_B + bcol * 2;
                asm volatile("ldmatrix.sync.aligned.m8n8.x2.shared.b16 {%0,%1}, [%2];"
                             : "=r"(bh[ni][0]), "=r"(bh[ni][1]) : "r"(ab));
                uint32_t ab2 = ab + TILE_W;
                asm volatile("ldmatrix.sync.aligned.m8n8.x2.shared.b16 {%0,%1}, [%2];"
                             : "=r"(bl[ni][0]), "=r"(bl[ni][1]) : "r"(ab2));
            }
            const uint32_t arow = wy * 128 + (lane & 15);
            const uint32_t acol = ks * 16 + (lane >> 4) * 8;
#pragma unroll
            for (int mi = 0; mi < 8; mi++) {
                uint32_t ah[4];
                uint32_t aa = sbase + (arow + mi * 16) * ROW_B + acol * 2;
                asm volatile("ldmatrix.sync.aligned.m8n8.x4.shared.b16 {%0,%1,%2,%3}, [%4];"
                             : "=r"(ah[0]), "=r"(ah[1]), "=r"(ah[2]), "=r"(ah[3]) : "r"(aa));
#pragma unroll
                for (int ni = 0; ni < 4; ni++) mma16816h(acc[mi][ni], ah, bh[ni]);
#pragma unroll
                for (int ni = 0; ni < 4; ni++) mma16816h(acc[mi][ni], ah, bl[ni]);
            }
        }
    }

    __half* Pz = Pout + (size_t)z * MSZ;
    const int g = lane >> 2, tg = lane & 3;
#pragma unroll
    for (int mi = 0; mi < 8; mi++) {
        int row0 = by + wy * 128 + mi * 16 + g;
#pragma unroll
        for (int ni = 0; ni < 4; ni++) {
            int col = bx + wx * 32 + ni * 8 + tg * 2;
            float b0v = __ldg(bias + col), b1v = __ldg(bias + col + 1);
            *(uint32_t*)&Pz[(size_t)row0 * EMB + col] =
                pack_h2((acc[mi][ni][0] + b0v) * scale, (acc[mi][ni][1] + b1v) * scale);
            *(uint32_t*)&Pz[(size_t)(row0 + 8) * EMB + col] =
                pack_h2((acc[mi][ni][2] + b0v) * scale, (acc[mi][ni][3] + b1v) * scale);
        }
    }
}

// ---------------- O GEMM: A fp16 (context), W fp16 hi/lo, out fp32 ----------
__global__ __launch_bounds__(256) void gemm_o(
    const __half* __restrict__ A, const __half* __restrict__ Whi,
    const __half* __restrict__ Wlo, const float* __restrict__ bias,
    float* __restrict__ Cf)
{
    extern __shared__ char smc[];
    const int tid = threadIdx.x;
    const int lane = tid & 31, w = tid >> 5;
    const int wy = w >> 2, wx = w & 3;
    const int bx = blockIdx.x * 128, by = blockIdx.y * 256;
    const uint32_t sbase = smem_u32(smc);

    const char* asrc = (const char*)(A + (size_t)by * EMB);
    const char* wsrc[2] = {
        (const char*)(Whi + (size_t)bx * EMB),
        (const char*)(Wlo + (size_t)bx * EMB)};

    auto prefetch = [&](int kb, int st) {
        // A: 256 rows x 4 x 16B
#pragma unroll
        for (int s = 0; s < 4; s++) {
            int idx = tid + s * 256;
            int r = idx >> 2, c = idx & 3;
            const char* src = asrc + ((size_t)r * EMB + (size_t)kb * BK) * 2 + c * 16;
            uint32_t dst = sbase + (uint32_t)st * O_STAGE + (uint32_t)r * ROW_B + c * 16;
            asm volatile("cp.async.cg.shared.global [%0], [%1], 16;"
                         :: "r"(dst), "l"(src));
        }
        // W hi/lo: 128 rows x 4 x 16B each
#pragma unroll
        for (int t = 0; t < 2; t++)
#pragma unroll
            for (int s = 0; s < 2; s++) {
                int idx = tid + s * 256;
                int r = idx >> 2, c = idx & 3;
                const char* src = wsrc[t] + ((size_t)r * EMB + (size_t)kb * BK) * 2 + c * 16;
                uint32_t dst = sbase + (uint32_t)st * O_STAGE + A_TILE
                             + t * TILE_W + (uint32_t)r * ROW_B + c * 16;
                asm volatile("cp.async.cg.shared.global [%0], [%1], 16;"
                             :: "r"(dst), "l"(src));
            }
        asm volatile("cp.async.commit_group;");
    };

    float acc[8][4][4];
#pragma unroll
    for (int mi = 0; mi < 8; mi++)
#pragma unroll
        for (int ni = 0; ni < 4; ni++)
#pragma unroll
            for (int j = 0; j < 4; j++) acc[mi][ni][j] = 0.f;

    prefetch(0, 0);

    for (int kb = 0; kb < NCHUNK; kb++) {
        asm volatile("cp.async.wait_group 0;");
        __syncthreads();
        if (kb + 1 < NCHUNK) prefetch(kb + 1, (kb + 1) & 1);
        const uint32_t st = sbase + (uint32_t)(kb & 1) * O_STAGE;

#pragma unroll
        for (int ks = 0; ks < 2; ks++) {
            uint32_t bh[4][2], bl[4][2];
            const uint32_t brow = wx * 32 + (lane & 7);
            const uint32_t bcol = ks * 16 + ((lane >> 3) & 1) * 8;
#pragma unroll
            for (int ni = 0; ni < 4; ni++) {
                uint32_t ab = st + A_TILE + (brow + ni * 8) * ROW_B + bcol * 2;
                asm volatile("ldmatrix.sync.aligned.m8n8.x2.shared.b16 {%0,%1}, [%2];"
                             : "=r"(bh[ni][0]), "=r"(bh[ni][1]) : "r"(ab));
                uint32_t ab2 = ab + TILE_W;
                asm volatile("ldmatrix.sync.aligned.m8n8.x2.shared.b16 {%0,%1}, [%2];"
                             : "=r"(bl[ni][0]), "=r"(bl[ni][1]) : "r"(ab2));
            }
            const uint32_t arow = wy * 128 + (lane & 15);
            const uint32_t acol = ks * 16 + (lane >> 4) * 8;
#pragma unroll
            for (int mi = 0; mi < 8; mi++) {
                uint32_t ah[4];
                uint32_t aa = st + (arow + mi * 16) * ROW_B + acol * 2;
                asm volatile("ldmatrix.sync.aligned.m8n8.x4.shared.b16 {%0,%1,%2,%3}, [%4];"
                             : "=r"(ah[0]), "=r"(ah[1]), "=r"(ah[2]), "=r"(ah[3]) : "r"(aa));
#pragma unroll
                for (int ni = 0; ni < 4; ni++) mma16816h(acc[mi][ni], ah, bh[ni]);
#pragma unroll
                for (int ni = 0; ni < 4; ni++) mma16816h(acc[mi][ni], ah, bl[ni]);
            }
        }
    }

    const int g = lane >> 2, tg = lane & 3;
#pragma unroll
    for (int mi = 0; mi < 8; mi++) {
        int row0 = by + wy * 128 + mi * 16 + g;
#pragma unroll
        for (int ni = 0; ni < 4; ni++) {
            int col = bx + wx * 32 + ni * 8 + tg * 2;
            float b0v = __ldg(bias + col), b1v = __ldg(bias + col + 1);
            float2 o0 = {acc[mi][ni][0] + b0v, acc[mi][ni][1] + b1v};
            float2 o1 = {acc[mi][ni][2] + b0v, acc[mi][ni][3] + b1v};
            *(float2*)&Cf[(size_t)row0 * EMB + col] = o0;
            *(float2*)&Cf[(size_t)(row0 + 8) * EMB + col] = o1;
        }
    }
}

// ---------------- fp16 flash attention (R13 verbatim) -----------------------
#define AT_ROW 144
#define AT_QTILE (128*AT_ROW)
#define AT_TILE (64*AT_ROW)
#define AT_STAGE (2*AT_TILE)
#define ATT_SMEM (2*AT_STAGE)

__global__ __launch_bounds__(256) void attn_mma(
    const __half* __restrict__ Ph_, __half* __restrict__ Ch_)
{
    extern __shared__ char smc[];
    const uint32_t sbase = smem_u32(smc);
    const int tid = threadIdx.x, lane = tid & 31, w = tid >> 5;
    const int b = blockIdx.z, h = blockIdx.y;
    const int q0 = blockIdx.x * 128;
    const size_t base_e = ((size_t)b * SEQ) * EMB + h * HD;

    const __half* Qh_ = Ph_;
    const __half* Kh_ = Ph_ + MSZ;
    const __half* Vh_ = Ph_ + 2*MSZ;

#pragma unroll
    for (int s = 0; s < 4; s++) {
        int idx = tid + s * 256;
        int r = idx >> 3, c = idx & 7;
        const char* src = (const char*)(Qh_ + base_e + (size_t)(q0 + r) * EMB) + c * 16;
        uint32_t dst = sbase + (uint32_t)r * AT_ROW + c * 16;
        asm volatile("cp.async.cg.shared.global [%0], [%1], 16;" :: "r"(dst), "l"(src));
    }
    asm volatile("cp.async.commit_group;");
    asm volatile("cp.async.wait_group 0;");
    __syncthreads();

    uint32_t qh[4][4];
    {
        const uint32_t arow = w * 16 + (lane & 15);
#pragma unroll
        for (int ks = 0; ks < 4; ks++) {
            uint32_t aa = sbase + arow * AT_ROW + (ks * 16 + (lane >> 4) * 8) * 2;
            asm volatile("ldmatrix.sync.aligned.m8n8.x4.shared.b16 {%0,%1,%2,%3}, [%4];"
                : "=r"(qh[ks][0]), "=r"(qh[ks][1]), "=r"(qh[ks][2]), "=r"(qh[ks][3]) : "r"(aa));
        }
    }
    __syncthreads();

    const __half* kvsrc[2] = {Kh_, Vh_};
    auto prefetch = [&](int kb, int st) {
#pragma unroll
        for (int s = 0; s < 4; s++) {
            int idx = tid + s * 256;
            int t = idx >> 9, rem = idx & 511;
            int r = rem >> 3, c = rem & 7;
            const char* src = (const char*)(kvsrc[t] + base_e + (size_t)(kb * 64 + r) * EMB) + c * 16;
            uint32_t dst = sbase + (uint32_t)st * AT_STAGE + t * AT_TILE
                         + (uint32_t)r * AT_ROW + c * 16;
            asm volatile("cp.async.cg.shared.global [%0], [%1], 16;" :: "r"(dst), "l"(src));
        }
        asm volatile("cp.async.commit_group;");
    };

    float oacc[8][4];
    float m_i[2] = {-1e30f, -1e30f}, l_i[2] = {0.f, 0.f};
#pragma unroll
    for (int j = 0; j < 8; j++)
#pragma unroll
        for (int c = 0; c < 4; c++) oacc[j][c] = 0.f;

    prefetch(0, 0);

    for (int kb = 0; kb < SEQ/64; kb++) {
        asm volatile("cp.async.wait_group 0;");
        __syncthreads();
        if (kb + 1 < SEQ/64) prefetch(kb + 1, (kb + 1) & 1);
        const uint32_t st = sbase + (uint32_t)(kb & 1) * AT_STAGE;

        float sacc[8][4];
#pragma unroll
        for (int j = 0; j < 8; j++)
#pragma unroll
            for (int c = 0; c < 4; c++) sacc[j][c] = 0.f;

#pragma unroll
        for (int ks = 0; ks < 4; ks++) {
            const uint32_t bcol = ks * 16 + ((lane >> 3) & 1) * 8;
#pragma unroll
            for (int jg = 0; jg < 2; jg++) {
                uint32_t bh[4][2];
#pragma unroll
                for (int jj = 0; jj < 4; jj++) {
                    uint32_t ab = st + ((jg*4+jj) * 8 + (lane & 7)) * AT_ROW + bcol * 2;
                    asm volatile("ldmatrix.sync.aligned.m8n8.x2.shared.b16 {%0,%1}, [%2];"
                                 : "=r"(bh[jj][0]), "=r"(bh[jj][1]) : "r"(ab));
                }
#pragma unroll
                for (int jj = 0; jj < 4; jj++) mma16816h(sacc[jg*4+jj], qh[ks], bh[jj]);
            }
        }

#pragma unroll
        for (int rh = 0; rh < 2; rh++) {
            float mx = -1e30f;
#pragma unroll
            for (int j = 0; j < 8; j++)
                mx = fmaxf(mx, fmaxf(sacc[j][2*rh], sacc[j][2*rh+1]));
            mx = fmaxf(mx, __shfl_xor_sync(0xffffffffu, mx, 1));
            mx = fmaxf(mx, __shfl_xor_sync(0xffffffffu, mx, 2));
            float m_new = fmaxf(m_i[rh], mx);
            float corr = __expf(m_i[rh] - m_new);
            float sum = 0.f;
#pragma unroll
            for (int j = 0; j < 8; j++) {
                float p0 = __expf(sacc[j][2*rh]   - m_new);
                float p1 = __expf(sacc[j][2*rh+1] - m_new);
                sacc[j][2*rh] = p0; sacc[j][2*rh+1] = p1;
                sum += p0 + p1;
            }
            sum += __shfl_xor_sync(0xffffffffu, sum, 1);
            sum += __shfl_xor_sync(0xffffffffu, sum, 2);
            l_i[rh] = l_i[rh] * corr + sum;
            m_i[rh] = m_new;
#pragma unroll
            for (int j = 0; j < 8; j++) {
                oacc[j][2*rh]   *= corr;
                oacc[j][2*rh+1] *= corr;
            }
        }

        uint32_t phi[4][4];
#pragma unroll
        for (int ks = 0; ks < 4; ks++) {
            phi[ks][0] = pack_h2(sacc[2*ks][0],   sacc[2*ks][1]);
            phi[ks][1] = pack_h2(sacc[2*ks][2],   sacc[2*ks][3]);
            phi[ks][2] = pack_h2(sacc[2*ks+1][0], sacc[2*ks+1][1]);
            phi[ks][3] = pack_h2(sacc[2*ks+1][2], sacc[2*ks+1][3]);
        }

#pragma unroll
        for (int ks = 0; ks < 4; ks++) {
            const uint32_t vrow = ks * 16 + (lane & 15);
            const uint32_t vsub = (lane >> 4) * 8;
#pragma unroll
            for (int jp = 0; jp < 2; jp++) {
                uint32_t vh0[4], vh1[4];
                uint32_t va = st + AT_TILE + vrow * AT_ROW + ((2*jp) * 16 + vsub) * 2;
                asm volatile("ldmatrix.sync.aligned.m8n8.x4.trans.shared.b16 {%0,%1,%2,%3}, [%4];"
                    : "=r"(vh0[0]), "=r"(vh0[1]), "=r"(vh0[2]), "=r"(vh0[3]) : "r"(va));
                uint32_t vb = va + 32;
                asm volatile("ldmatrix.sync.aligned.m8n8.x4.trans.shared.b16 {%0,%1,%2,%3}, [%4];"
                    : "=r"(vh1[0]), "=r"(vh1[1]), "=r"(vh1[2]), "=r"(vh1[3]) : "r"(vb));
                mma16816h(oacc[4*jp],   phi[ks], &vh0[0]);
                mma16816h(oacc[4*jp+1], phi[ks], &vh0[2]);
                mma16816h(oacc[4*jp+2], phi[ks], &vh1[0]);
                mma16816h(oacc[4*jp+3], phi[ks], &vh1[2]);
            }
        }
    }

    const int g = lane >> 2, tg = lane & 3;
#pragma unroll
    for (int rh = 0; rh < 2; rh++) {
        float inv = 1.0f / l_i[rh];
        int row = q0 + w * 16 + g + 8 * rh;
        size_t ro = base_e + (size_t)row * EMB;
#pragma unroll
        for (int j = 0; j < 8; j++) {
            int col = j * 8 + tg * 2;
            *(uint32_t*)&Ch_[ro + col] =
                pack_h2(oacc[j][2*rh] * inv, oacc[j][2*rh+1] * inv);
        }
    }
}

// ---------------------------------------------------------------------------
extern "C" void kernel_launch(void* const* d_in, const int* in_sizes, int n_in,
                              void* d_out, int out_size)
{
    const float* q  = (const float*)d_in[0];
    const float* k  = (const float*)d_in[1];
    const float* v  = (const float*)d_in[2];
    const float* Wq = (const float*)d_in[3];
    const float* bq = (const float*)d_in[4];
    const float* Wk = (const float*)d_in[5];
    const float* bk = (const float*)d_in[6];
    const float* Wv = (const float*)d_in[7];
    const float* bv = (const float*)d_in[8];
    const float* Wo = (const float*)d_in[9];
    const float* bo = (const float*)d_in[10];
    float* out = (float*)d_out;

    __half *wh, *wl, *ph, *ch;
    cudaGetSymbolAddress((void**)&wh, g_w_h);
    cudaGetSymbolAddress((void**)&wl, g_w_l);
    cudaGetSymbolAddress((void**)&ph, g_P_hi);
    cudaGetSymbolAddress((void**)&ch, g_Ch);

    cudaFuncSetAttribute(gemm_qkv,
        cudaFuncAttributeMaxDynamicSharedMemorySize, QKV_SMEM);
    cudaFuncSetAttribute(gemm_o,
        cudaFuncAttributeMaxDynamicSharedMemorySize, O_SMEM);
    cudaFuncSetAttribute(attn_mma,
        cudaFuncAttributeMaxDynamicSharedMemorySize, ATT_SMEM);

    SplitSrc ss;
    ss.p[0] = (const float4*)Wq; ss.p[1] = (const float4*)Wk;
    ss.p[2] = (const float4*)Wv; ss.p[3] = (const float4*)Wo;
    split_w<<<dim3((unsigned)(WSZ/4/256), 4), 256>>>(ss, (uint2*)wh, (uint2*)wl);

    const float scaling = 0.125f;
    gemm_qkv<<<dim3(EMB/128, M_TOT/256, 3), 256, QKV_SMEM>>>(
        q, k, v, wh, wl, bq, bk, bv, scaling, ph);

    attn_mma<<<dim3(SEQ/128, NH, BSZ), 256, ATT_SMEM>>>(ph, ch);

    gemm_o<<<dim3(EMB/128, M_TOT/256, 1), 256, O_SMEM>>>(
        ch, wh + 3*WSZ, wl + 3*WSZ, bo, out);
}

// round 15
// speedup vs baseline: 1.3502x; 1.3502x over previous
#include <cuda_runtime.h>
#include <cuda_fp16.h>
#include <cstdint>
#include <math.h>

#define BSZ 8
#define SEQ 1024
#define EMB 1024
#define NH 16
#define HD 64
#define M_TOT (BSZ*SEQ)   // 8192
#define MSZ ((size_t)M_TOT*EMB)
#define WSZ ((size_t)EMB*EMB)

__device__ __half g_w_h[4*WSZ];     // weights hi
__device__ __half g_w_l[4*WSZ];     // weights lo (only Wo's is consumed)
__device__ __half g_P_hi[3*MSZ];    // projected Q/K/V (fp16)
__device__ __half g_Ch[MSZ];        // attention context (fp16)

__device__ __forceinline__ uint32_t smem_u32(const void* p) {
    uint32_t a;
    asm("{ .reg .u64 t; cvta.to.shared.u64 t, %1; cvt.u32.u64 %0, t; }"
        : "=r"(a) : "l"(p));
    return a;
}

__device__ __forceinline__ void mma16816h(float* c, const uint32_t* a, const uint32_t* b) {
    asm volatile(
        "mma.sync.aligned.m16n8k16.row.col.f32.f16.f16.f32 "
        "{%0,%1,%2,%3}, {%4,%5,%6,%7}, {%8,%9}, {%0,%1,%2,%3};"
        : "+f"(c[0]), "+f"(c[1]), "+f"(c[2]), "+f"(c[3])
        : "r"(a[0]), "r"(a[1]), "r"(a[2]), "r"(a[3]), "r"(b[0]), "r"(b[1]));
}

__device__ __forceinline__ void split2h(float x, float y, uint32_t& hi, uint32_t& lo) {
    __half hx = __float2half_rn(x), hy = __float2half_rn(y);
    float rx = x - __half2float(hx), ry = y - __half2float(hy);
    __half2 hp = {hx, hy};
    __half2 lp = {__float2half_rn(rx), __float2half_rn(ry)};
    hi = *reinterpret_cast<uint32_t*>(&hp);
    lo = *reinterpret_cast<uint32_t*>(&lp);
}
__device__ __forceinline__ uint32_t pack_h2(float x, float y) {
    __half2 p = {__float2half_rn(x), __float2half_rn(y)};
    return *reinterpret_cast<uint32_t*>(&p);
}

// ---------------- weight fp32 -> fp16 hi/lo split (4 tensors) ---------------
struct SplitSrc { const float4* p[4]; };

__global__ __launch_bounds__(256) void split_w(
    SplitSrc s, uint2* __restrict__ wh, uint2* __restrict__ wl)
{
    const int seg = blockIdx.y;
    const int i = blockIdx.x * 256 + threadIdx.x;
    if (i >= (int)(WSZ/4)) return;
    float4 v = s.p[seg][i];
    uint32_t h0, l0, h1, l1;
    split2h(v.x, v.y, h0, l0);
    split2h(v.z, v.w, h1, l1);
    uint2 ho = {h0, h1}, loo = {l0, l1};
    size_t off = (size_t)seg * (WSZ/4) + i;
    wh[off] = ho; wl[off] = loo;
}

// ---------------- QKV GEMM: A fp32 (fused convert), W fp16 HI ONLY ----------
// P = scale*(A @ Wh^T + bias), fp16 out. 1 MMA per (mi,ni,ks).
// Smem: A tile single-buffered at 0; W-hi double-staged after it.
#define BK 32
#define NCHUNK (EMB/BK)
#define ROW_B 80
#define TILE_BYT (128*ROW_B)       // 10240
#define QKV_SMEM (3*TILE_BYT)      // A + 2 stages x Wh = 30720

__global__ __launch_bounds__(256) void gemm_qkv(
    const float* __restrict__ in_q, const float* __restrict__ in_k,
    const float* __restrict__ in_v,
    const __half* __restrict__ Wbase_h,
    const float* __restrict__ b0, const float* __restrict__ b1,
    const float* __restrict__ b2, float scale0,
    __half* __restrict__ Pout)
{
    extern __shared__ char smc[];
    const int z = blockIdx.z;
    const int tid = threadIdx.x;
    const int lane = tid & 31, w = tid >> 5;
    const int wy = w >> 2, wx = w & 3;
    const int bx = blockIdx.x * 128, by = blockIdx.y * 128;
    const uint32_t sbase = smem_u32(smc);

    const float* A = (z == 0) ? in_q : ((z == 1) ? in_k : in_v);
    const float* Asrc = A + (size_t)by * EMB;
    const __half* Whi = Wbase_h + (size_t)z * WSZ;
    const float* bias = (z == 0) ? b0 : ((z == 1) ? b1 : b2);
    const float scale = (z == 0) ? scale0 : 1.0f;

    const char* wsrc = (const char*)(Whi + (size_t)bx * EMB);

    auto prefetchW = [&](int kb, int st) {
#pragma unroll
        for (int s = 0; s < 2; s++) {
            int idx = tid + s * 256;
            int r = idx >> 2, c = idx & 3;
            const char* src = wsrc + ((size_t)r * EMB + (size_t)kb * BK) * 2 + c * 16;
            uint32_t dst = sbase + TILE_BYT + (uint32_t)st * TILE_BYT
                         + (uint32_t)r * ROW_B + c * 16;
            asm volatile("cp.async.cg.shared.global [%0], [%1], 16;"
                         :: "r"(dst), "l"(src));
        }
        asm volatile("cp.async.commit_group;");
    };

    float4 rA[2][2];
    auto ldgA = [&](int kb) {
#pragma unroll
        for (int s = 0; s < 2; s++) {
            int idx = tid + s * 256;
            int r = idx >> 2, c = idx & 3;
            const float* p = Asrc + (size_t)r * EMB + kb * BK + c * 8;
            rA[s][0] = *(const float4*)p;
            rA[s][1] = *(const float4*)(p + 4);
        }
    };
    auto stsA = [&]() {
#pragma unroll
        for (int s = 0; s < 2; s++) {
            int idx = tid + s * 256;
            int r = idx >> 2, c = idx & 3;
            uint4 val;
            val.x = pack_h2(rA[s][0].x, rA[s][0].y);
            val.y = pack_h2(rA[s][0].z, rA[s][0].w);
            val.z = pack_h2(rA[s][1].x, rA[s][1].y);
            val.w = pack_h2(rA[s][1].z, rA[s][1].w);
            *(uint4*)(smc + (uint32_t)r * ROW_B + c * 16) = val;
        }
    };

    float acc[4][4][4];
#pragma unroll
    for (int mi = 0; mi < 4; mi++)
#pragma unroll
        for (int ni = 0; ni < 4; ni++)
#pragma unroll
            for (int j = 0; j < 4; j++) acc[mi][ni][j] = 0.f;

    prefetchW(0, 0);
    ldgA(0);

    for (int kb = 0; kb < NCHUNK; kb++) {
        asm volatile("cp.async.wait_group 0;");
        __syncthreads();          // W(kb) landed; all LDSM of A(kb-1) retired
        stsA();
        __syncthreads();          // A(kb) visible
        if (kb + 1 < NCHUNK) { prefetchW(kb + 1, (kb + 1) & 1); ldgA(kb + 1); }
        const uint32_t wb = sbase + TILE_BYT + (uint32_t)(kb & 1) * TILE_BYT;

#pragma unroll
        for (int ks = 0; ks < 2; ks++) {
            uint32_t bh[4][2];
            const uint32_t brow = wx * 32 + (lane & 7);
            const uint32_t bcol = ks * 16 + ((lane >> 3) & 1) * 8;
#pragma unroll
            for (int ni = 0; ni < 4; ni++) {
                uint32_t ab = wb + (brow + ni * 8) * ROW_B + bcol * 2;
                asm volatile("ldmatrix.sync.aligned.m8n8.x2.shared.b16 {%0,%1}, [%2];"
                             : "=r"(bh[ni][0]), "=r"(bh[ni][1]) : "r"(ab));
            }
            const uint32_t arow = wy * 64 + (lane & 15);
            const uint32_t acol = ks * 16 + (lane >> 4) * 8;
            uint32_t ah[4][4];
#pragma unroll
            for (int mi = 0; mi < 4; mi++) {
                uint32_t aa = sbase + (arow + mi * 16) * ROW_B + acol * 2;
                asm volatile("ldmatrix.sync.aligned.m8n8.x4.shared.b16 {%0,%1,%2,%3}, [%4];"
                             : "=r"(ah[mi][0]), "=r"(ah[mi][1]), "=r"(ah[mi][2]), "=r"(ah[mi][3]) : "r"(aa));
            }
#pragma unroll
            for (int mi = 0; mi < 4; mi++)
#pragma unroll
                for (int ni = 0; ni < 4; ni++) mma16816h(acc[mi][ni], ah[mi], bh[ni]);
        }
    }

    __half* Pz = Pout + (size_t)z * MSZ;
    const int g = lane >> 2, tg = lane & 3;
#pragma unroll
    for (int mi = 0; mi < 4; mi++) {
        int row0 = by + wy * 64 + mi * 16 + g;
#pragma unroll
        for (int ni = 0; ni < 4; ni++) {
            int col = bx + wx * 32 + ni * 8 + tg * 2;
            float b0v = __ldg(bias + col), b1v = __ldg(bias + col + 1);
            *(uint32_t*)&Pz[(size_t)row0 * EMB + col] =
                pack_h2((acc[mi][ni][0] + b0v) * scale, (acc[mi][ni][1] + b1v) * scale);
            *(uint32_t*)&Pz[(size_t)(row0 + 8) * EMB + col] =
                pack_h2((acc[mi][ni][2] + b0v) * scale, (acc[mi][ni][3] + b1v) * scale);
        }
    }
}

// ---------------- O GEMM: A fp16 (context), W fp16 hi/lo, out fp32 ----------
#define O_STAGE (3*TILE_BYT)
#define O_SMEM (2*O_STAGE)         // 61440

__global__ __launch_bounds__(256) void gemm_o(
    const __half* __restrict__ A, const __half* __restrict__ Whi,
    const __half* __restrict__ Wlo, const float* __restrict__ bias,
    float* __restrict__ Cf)
{
    extern __shared__ char smc[];
    const int tid = threadIdx.x;
    const int lane = tid & 31, w = tid >> 5;
    const int wy = w >> 2, wx = w & 3;
    const int bx = blockIdx.x * 128, by = blockIdx.y * 128;
    const uint32_t sbase = smem_u32(smc);

    const char* gsrc[3] = {
        (const char*)(A   + (size_t)by * EMB),
        (const char*)(Whi + (size_t)bx * EMB),
        (const char*)(Wlo + (size_t)bx * EMB)};

    auto prefetch = [&](int kb, int st) {
#pragma unroll
        for (int t = 0; t < 3; t++)
#pragma unroll
            for (int s = 0; s < 2; s++) {
                int idx = tid + s * 256;
                int r = idx >> 2, c = idx & 3;
                const char* src = gsrc[t] + ((size_t)r * EMB + (size_t)kb * BK) * 2 + c * 16;
                uint32_t dst = sbase + (uint32_t)st * O_STAGE + t * TILE_BYT
                             + (uint32_t)r * ROW_B + c * 16;
                asm volatile("cp.async.cg.shared.global [%0], [%1], 16;"
                             :: "r"(dst), "l"(src));
            }
        asm volatile("cp.async.commit_group;");
    };

    float acc[4][4][4];
#pragma unroll
    for (int mi = 0; mi < 4; mi++)
#pragma unroll
        for (int ni = 0; ni < 4; ni++)
#pragma unroll
            for (int j = 0; j < 4; j++) acc[mi][ni][j] = 0.f;

    prefetch(0, 0);

    for (int kb = 0; kb < NCHUNK; kb++) {
        asm volatile("cp.async.wait_group 0;");
        __syncthreads();
        if (kb + 1 < NCHUNK) prefetch(kb + 1, (kb + 1) & 1);
        const uint32_t st = sbase + (uint32_t)(kb & 1) * O_STAGE;

#pragma unroll
        for (int ks = 0; ks < 2; ks++) {
            uint32_t bh[4][2], bl[4][2];
            const uint32_t brow = wx * 32 + (lane & 7);
            const uint32_t bcol = ks * 16 + ((lane >> 3) & 1) * 8;
#pragma unroll
            for (int ni = 0; ni < 4; ni++) {
                uint32_t ab = st + 1 * TILE_BYT + (brow + ni * 8) * ROW_B + bcol * 2;
                asm volatile("ldmatrix.sync.aligned.m8n8.x2.shared.b16 {%0,%1}, [%2];"
                             : "=r"(bh[ni][0]), "=r"(bh[ni][1]) : "r"(ab));
                uint32_t ab2 = ab + TILE_BYT;
                asm volatile("ldmatrix.sync.aligned.m8n8.x2.shared.b16 {%0,%1}, [%2];"
                             : "=r"(bl[ni][0]), "=r"(bl[ni][1]) : "r"(ab2));
            }
            const uint32_t arow = wy * 64 + (lane & 15);
            const uint32_t acol = ks * 16 + (lane >> 4) * 8;
            uint32_t ah[4][4];
#pragma unroll
            for (int mi = 0; mi < 4; mi++) {
                uint32_t aa = st + (arow + mi * 16) * ROW_B + acol * 2;
                asm volatile("ldmatrix.sync.aligned.m8n8.x4.shared.b16 {%0,%1,%2,%3}, [%4];"
                             : "=r"(ah[mi][0]), "=r"(ah[mi][1]), "=r"(ah[mi][2]), "=r"(ah[mi][3]) : "r"(aa));
            }
#pragma unroll
            for (int mi = 0; mi < 4; mi++)
#pragma unroll
                for (int ni = 0; ni < 4; ni++) mma16816h(acc[mi][ni], ah[mi], bh[ni]);
#pragma unroll
            for (int mi = 0; mi < 4; mi++)
#pragma unroll
                for (int ni = 0; ni < 4; ni++) mma16816h(acc[mi][ni], ah[mi], bl[ni]);
        }
    }

    const int g = lane >> 2, tg = lane & 3;
#pragma unroll
    for (int mi = 0; mi < 4; mi++) {
        int row0 = by + wy * 64 + mi * 16 + g;
#pragma unroll
        for (int ni = 0; ni < 4; ni++) {
            int col = bx + wx * 32 + ni * 8 + tg * 2;
            float b0v = __ldg(bias + col), b1v = __ldg(bias + col + 1);
            float2 o0 = {acc[mi][ni][0] + b0v, acc[mi][ni][1] + b1v};
            float2 o1 = {acc[mi][ni][2] + b0v, acc[mi][ni][3] + b1v};
            *(float2*)&Cf[(size_t)row0 * EMB + col] = o0;
            *(float2*)&Cf[(size_t)(row0 + 8) * EMB + col] = o1;
        }
    }
}

// ---------------- fp16 flash attention (R13) --------------------------------
#define AT_ROW 144
#define AT_TILE (64*AT_ROW)
#define AT_STAGE (2*AT_TILE)
#define ATT_SMEM (2*AT_STAGE)      // 36864

__global__ __launch_bounds__(256) void attn_mma(
    const __half* __restrict__ Ph_, __half* __restrict__ Ch_)
{
    extern __shared__ char smc[];
    const uint32_t sbase = smem_u32(smc);
    const int tid = threadIdx.x, lane = tid & 31, w = tid >> 5;
    const int b = blockIdx.z, h = blockIdx.y;
    const int q0 = blockIdx.x * 128;
    const size_t base_e = ((size_t)b * SEQ) * EMB + h * HD;

    const __half* Qh_ = Ph_;
    const __half* Kh_ = Ph_ + MSZ;
    const __half* Vh_ = Ph_ + 2*MSZ;

    // ---- stage Q hi (consumed into regs below) ----
#pragma unroll
    for (int s = 0; s < 4; s++) {
        int idx = tid + s * 256;
        int r = idx >> 3, c = idx & 7;
        const char* src = (const char*)(Qh_ + base_e + (size_t)(q0 + r) * EMB) + c * 16;
        uint32_t dst = sbase + (uint32_t)r * AT_ROW + c * 16;
        asm volatile("cp.async.cg.shared.global [%0], [%1], 16;" :: "r"(dst), "l"(src));
    }
    asm volatile("cp.async.commit_group;");
    asm volatile("cp.async.wait_group 0;");
    __syncthreads();

    uint32_t qh[4][4];
    {
        const uint32_t arow = w * 16 + (lane & 15);
#pragma unroll
        for (int ks = 0; ks < 4; ks++) {
            uint32_t aa = sbase + arow * AT_ROW + (ks * 16 + (lane >> 4) * 8) * 2;
            asm volatile("ldmatrix.sync.aligned.m8n8.x4.shared.b16 {%0,%1,%2,%3}, [%4];"
                : "=r"(qh[ks][0]), "=r"(qh[ks][1]), "=r"(qh[ks][2]), "=r"(qh[ks][3]) : "r"(aa));
        }
    }
    __syncthreads();

    const __half* kvsrc[2] = {Kh_, Vh_};
    auto prefetch = [&](int kb, int st) {
#pragma unroll
        for (int s = 0; s < 4; s++) {
            int idx = tid + s * 256;
            int t = idx >> 9, rem = idx & 511;
            int r = rem >> 3, c = rem & 7;
            const char* src = (const char*)(kvsrc[t] + base_e + (size_t)(kb * 64 + r) * EMB) + c * 16;
            uint32_t dst = sbase + (uint32_t)st * AT_STAGE + t * AT_TILE
                         + (uint32_t)r * AT_ROW + c * 16;
            asm volatile("cp.async.cg.shared.global [%0], [%1], 16;" :: "r"(dst), "l"(src));
        }
        asm volatile("cp.async.commit_group;");
    };

    float oacc[8][4];
    float m_i[2] = {-1e30f, -1e30f}, l_i[2] = {0.f, 0.f};
#pragma unroll
    for (int j = 0; j < 8; j++)
#pragma unroll
        for (int c = 0; c < 4; c++) oacc[j][c] = 0.f;

    prefetch(0, 0);

    for (int kb = 0; kb < SEQ/64; kb++) {
        asm volatile("cp.async.wait_group 0;");
        __syncthreads();
        if (kb + 1 < SEQ/64) prefetch(kb + 1, (kb + 1) & 1);
        const uint32_t st = sbase + (uint32_t)(kb & 1) * AT_STAGE;

        float sacc[8][4];
#pragma unroll
        for (int j = 0; j < 8; j++)
#pragma unroll
            for (int c = 0; c < 4; c++) sacc[j][c] = 0.f;

#pragma unroll
        for (int ks = 0; ks < 4; ks++) {
            const uint32_t bcol = ks * 16 + ((lane >> 3) & 1) * 8;
#pragma unroll
            for (int jg = 0; jg < 2; jg++) {
                uint32_t bh[4][2];
#pragma unroll
                for (int jj = 0; jj < 4; jj++) {
                    uint32_t ab = st + ((jg*4+jj) * 8 + (lane & 7)) * AT_ROW + bcol * 2;
                    asm volatile("ldmatrix.sync.aligned.m8n8.x2.shared.b16 {%0,%1}, [%2];"
                                 : "=r"(bh[jj][0]), "=r"(bh[jj][1]) : "r"(ab));
                }
#pragma unroll
                for (int jj = 0; jj < 4; jj++) mma16816h(sacc[jg*4+jj], qh[ks], bh[jj]);
            }
        }

        // ---- online softmax ----
#pragma unroll
        for (int rh = 0; rh < 2; rh++) {
            float mx = -1e30f;
#pragma unroll
            for (int j = 0; j < 8; j++)
                mx = fmaxf(mx, fmaxf(sacc[j][2*rh], sacc[j][2*rh+1]));
            mx = fmaxf(mx, __shfl_xor_sync(0xffffffffu, mx, 1));
            mx = fmaxf(mx, __shfl_xor_sync(0xffffffffu, mx, 2));
            float m_new = fmaxf(m_i[rh], mx);
            float corr = __expf(m_i[rh] - m_new);
            float sum = 0.f;
#pragma unroll
            for (int j = 0; j < 8; j++) {
                float p0 = __expf(sacc[j][2*rh]   - m_new);
                float p1 = __expf(sacc[j][2*rh+1] - m_new);
                sacc[j][2*rh] = p0; sacc[j][2*rh+1] = p1;
                sum += p0 + p1;
            }
            sum += __shfl_xor_sync(0xffffffffu, sum, 1);
            sum += __shfl_xor_sync(0xffffffffu, sum, 2);
            l_i[rh] = l_i[rh] * corr + sum;
            m_i[rh] = m_new;
#pragma unroll
            for (int j = 0; j < 8; j++) {
                oacc[j][2*rh]   *= corr;
                oacc[j][2*rh+1] *= corr;
            }
        }

        uint32_t phi[4][4];
#pragma unroll
        for (int ks = 0; ks < 4; ks++) {
            phi[ks][0] = pack_h2(sacc[2*ks][0],   sacc[2*ks][1]);
            phi[ks][1] = pack_h2(sacc[2*ks][2],   sacc[2*ks][3]);
            phi[ks][2] = pack_h2(sacc[2*ks+1][0], sacc[2*ks+1][1]);
            phi[ks][3] = pack_h2(sacc[2*ks+1][2], sacc[2*ks+1][3]);
        }

#pragma unroll
        for (int ks = 0; ks < 4; ks++) {
            const uint32_t vrow = ks * 16 + (lane & 15);
            const uint32_t vsub = (lane >> 4) * 8;
#pragma unroll
            for (int jp = 0; jp < 2; jp++) {
                uint32_t vh0[4], vh1[4];
                uint32_t va = st + AT_TILE + vrow * AT_ROW + ((2*jp) * 16 + vsub) * 2;
                asm volatile("ldmatrix.sync.aligned.m8n8.x4.trans.shared.b16 {%0,%1,%2,%3}, [%4];"
                    : "=r"(vh0[0]), "=r"(vh0[1]), "=r"(vh0[2]), "=r"(vh0[3]) : "r"(va));
                uint32_t vb = va + 32;
                asm volatile("ldmatrix.sync.aligned.m8n8.x4.trans.shared.b16 {%0,%1,%2,%3}, [%4];"
                    : "=r"(vh1[0]), "=r"(vh1[1]), "=r"(vh1[2]), "=r"(vh1[3]) : "r"(vb));
                mma16816h(oacc[4*jp],   phi[ks], &vh0[0]);
                mma16816h(oacc[4*jp+1], phi[ks], &vh0[2]);
                mma16816h(oacc[4*jp+2], phi[ks], &vh1[0]);
                mma16816h(oacc[4*jp+3], phi[ks], &vh1[2]);
            }
        }
    }

    const int g = lane >> 2, tg = lane & 3;
#pragma unroll
    for (int rh = 0; rh < 2; rh++) {
        float inv = 1.0f / l_i[rh];
        int row = q0 + w * 16 + g + 8 * rh;
        size_t ro = base_e + (size_t)row * EMB;
#pragma unroll
        for (int j = 0; j < 8; j++) {
            int col = j * 8 + tg * 2;
            *(uint32_t*)&Ch_[ro + col] =
                pack_h2(oacc[j][2*rh] * inv, oacc[j][2*rh+1] * inv);
        }
    }
}

// ---------------------------------------------------------------------------
extern "C" void kernel_launch(void* const* d_in, const int* in_sizes, int n_in,
                              void* d_out, int out_size)
{
    const float* q  = (const float*)d_in[0];
    const float* k  = (const float*)d_in[1];
    const float* v  = (const float*)d_in[2];
    const float* Wq = (const float*)d_in[3];
    const float* bq = (const float*)d_in[4];
    const float* Wk = (const float*)d_in[5];
    const float* bk = (const float*)d_in[6];
    const float* Wv = (const float*)d_in[7];
    const float* bv = (const float*)d_in[8];
    const float* Wo = (const float*)d_in[9];
    const float* bo = (const float*)d_in[10];
    float* out = (float*)d_out;

    __half *wh, *wl, *ph, *ch;
    cudaGetSymbolAddress((void**)&wh, g_w_h);
    cudaGetSymbolAddress((void**)&wl, g_w_l);
    cudaGetSymbolAddress((void**)&ph, g_P_hi);
    cudaGetSymbolAddress((void**)&ch, g_Ch);

    cudaFuncSetAttribute(gemm_qkv,
        cudaFuncAttributeMaxDynamicSharedMemorySize, QKV_SMEM);
    cudaFuncSetAttribute(gemm_o,
        cudaFuncAttributeMaxDynamicSharedMemorySize, O_SMEM);
    cudaFuncSetAttribute(attn_mma,
        cudaFuncAttributeMaxDynamicSharedMemorySize, ATT_SMEM);

    SplitSrc ss;
    ss.p[0] = (const float4*)Wq; ss.p[1] = (const float4*)Wk;
    ss.p[2] = (const float4*)Wv; ss.p[3] = (const float4*)Wo;
    split_w<<<dim3((unsigned)(WSZ/4/256), 4), 256>>>(ss, (uint2*)wh, (uint2*)wl);

    const float scaling = 0.125f;
    gemm_qkv<<<dim3(EMB/128, M_TOT/128, 3), 256, QKV_SMEM>>>(
        q, k, v, wh, bq, bk, bv, scaling, ph);

    attn_mma<<<dim3(SEQ/128, NH, BSZ), 256, ATT_SMEM>>>(ph, ch);

    gemm_o<<<dim3(EMB/128, M_TOT/128, 1), 256, O_SMEM>>>(
        ch, wh + 3*WSZ, wl + 3*WSZ, bo, out);
}

// round 16
// speedup vs baseline: 1.5439x; 1.1434x over previous
#include <cuda_runtime.h>
#include <cuda_fp16.h>
#include <cstdint>
#include <math.h>

#define BSZ 8
#define SEQ 1024
#define EMB 1024
#define NH 16
#define HD 64
#define M_TOT (BSZ*SEQ)   // 8192
#define MSZ ((size_t)M_TOT*EMB)
#define WSZ ((size_t)EMB*EMB)

__device__ __half g_w_h[4*WSZ];     // weights (fp16)
__device__ __half g_P_hi[3*MSZ];    // projected Q/K/V (fp16)
__device__ __half g_Ch[MSZ];        // attention context (fp16)

__device__ __forceinline__ uint32_t smem_u32(const void* p) {
    uint32_t a;
    asm("{ .reg .u64 t; cvta.to.shared.u64 t, %1; cvt.u32.u64 %0, t; }"
        : "=r"(a) : "l"(p));
    return a;
}

__device__ __forceinline__ void mma16816h(float* c, const uint32_t* a, const uint32_t* b) {
    asm volatile(
        "mma.sync.aligned.m16n8k16.row.col.f32.f16.f16.f32 "
        "{%0,%1,%2,%3}, {%4,%5,%6,%7}, {%8,%9}, {%0,%1,%2,%3};"
        : "+f"(c[0]), "+f"(c[1]), "+f"(c[2]), "+f"(c[3])
        : "r"(a[0]), "r"(a[1]), "r"(a[2]), "r"(a[3]), "r"(b[0]), "r"(b[1]));
}

__device__ __forceinline__ uint32_t pack_h2(float x, float y) {
    __half2 p = {__float2half_rn(x), __float2half_rn(y)};
    return *reinterpret_cast<uint32_t*>(&p);
}

// ---------------- weight fp32 -> fp16 (4 tensors, hi only) ------------------
struct SplitSrc { const float4* p[4]; };

__global__ __launch_bounds__(256) void split_w(
    SplitSrc s, uint2* __restrict__ wh)
{
    const int seg = blockIdx.y;
    const int i = blockIdx.x * 256 + threadIdx.x;
    if (i >= (int)(WSZ/4)) return;
    float4 v = s.p[seg][i];
    uint2 ho;
    ho.x = pack_h2(v.x, v.y);
    ho.y = pack_h2(v.z, v.w);
    wh[(size_t)seg * (WSZ/4) + i] = ho;
}

// ---------------- QKV GEMM: A fp32 (fused convert), W fp16 ------------------
#define BK 32
#define NCHUNK (EMB/BK)
#define ROW_B 80
#define TILE_BYT (128*ROW_B)       // 10240
#define QKV_SMEM (3*TILE_BYT)      // A + 2 stages x Wh = 30720

__global__ __launch_bounds__(256) void gemm_qkv(
    const float* __restrict__ in_q, const float* __restrict__ in_k,
    const float* __restrict__ in_v,
    const __half* __restrict__ Wbase_h,
    const float* __restrict__ b0, const float* __restrict__ b1,
    const float* __restrict__ b2, float scale0,
    __half* __restrict__ Pout)
{
    extern __shared__ char smc[];
    const int z = blockIdx.z;
    const int tid = threadIdx.x;
    const int lane = tid & 31, w = tid >> 5;
    const int wy = w >> 2, wx = w & 3;
    const int bx = blockIdx.x * 128, by = blockIdx.y * 128;
    const uint32_t sbase = smem_u32(smc);

    const float* A = (z == 0) ? in_q : ((z == 1) ? in_k : in_v);
    const float* Asrc = A + (size_t)by * EMB;
    const __half* Whi = Wbase_h + (size_t)z * WSZ;
    const float* bias = (z == 0) ? b0 : ((z == 1) ? b1 : b2);
    const float scale = (z == 0) ? scale0 : 1.0f;

    const char* wsrc = (const char*)(Whi + (size_t)bx * EMB);

    auto prefetchW = [&](int kb, int st) {
#pragma unroll
        for (int s = 0; s < 2; s++) {
            int idx = tid + s * 256;
            int r = idx >> 2, c = idx & 3;
            const char* src = wsrc + ((size_t)r * EMB + (size_t)kb * BK) * 2 + c * 16;
            uint32_t dst = sbase + TILE_BYT + (uint32_t)st * TILE_BYT
                         + (uint32_t)r * ROW_B + c * 16;
            asm volatile("cp.async.cg.shared.global [%0], [%1], 16;"
                         :: "r"(dst), "l"(src));
        }
        asm volatile("cp.async.commit_group;");
    };

    float4 rA[2][2];
    auto ldgA = [&](int kb) {
#pragma unroll
        for (int s = 0; s < 2; s++) {
            int idx = tid + s * 256;
            int r = idx >> 2, c = idx & 3;
            const float* p = Asrc + (size_t)r * EMB + kb * BK + c * 8;
            rA[s][0] = *(const float4*)p;
            rA[s][1] = *(const float4*)(p + 4);
        }
    };
    auto stsA = [&]() {
#pragma unroll
        for (int s = 0; s < 2; s++) {
            int idx = tid + s * 256;
            int r = idx >> 2, c = idx & 3;
            uint4 val;
            val.x = pack_h2(rA[s][0].x, rA[s][0].y);
            val.y = pack_h2(rA[s][0].z, rA[s][0].w);
            val.z = pack_h2(rA[s][1].x, rA[s][1].y);
            val.w = pack_h2(rA[s][1].z, rA[s][1].w);
            *(uint4*)(smc + (uint32_t)r * ROW_B + c * 16) = val;
        }
    };

    float acc[4][4][4];
#pragma unroll
    for (int mi = 0; mi < 4; mi++)
#pragma unroll
        for (int ni = 0; ni < 4; ni++)
#pragma unroll
            for (int j = 0; j < 4; j++) acc[mi][ni][j] = 0.f;

    prefetchW(0, 0);
    ldgA(0);

    for (int kb = 0; kb < NCHUNK; kb++) {
        asm volatile("cp.async.wait_group 0;");
        __syncthreads();
        stsA();
        __syncthreads();
        if (kb + 1 < NCHUNK) { prefetchW(kb + 1, (kb + 1) & 1); ldgA(kb + 1); }
        const uint32_t wb = sbase + TILE_BYT + (uint32_t)(kb & 1) * TILE_BYT;

#pragma unroll
        for (int ks = 0; ks < 2; ks++) {
            uint32_t bh[4][2];
            const uint32_t brow = wx * 32 + (lane & 7);
            const uint32_t bcol = ks * 16 + ((lane >> 3) & 1) * 8;
#pragma unroll
            for (int ni = 0; ni < 4; ni++) {
                uint32_t ab = wb + (brow + ni * 8) * ROW_B + bcol * 2;
                asm volatile("ldmatrix.sync.aligned.m8n8.x2.shared.b16 {%0,%1}, [%2];"
                             : "=r"(bh[ni][0]), "=r"(bh[ni][1]) : "r"(ab));
            }
            const uint32_t arow = wy * 64 + (lane & 15);
            const uint32_t acol = ks * 16 + (lane >> 4) * 8;
            uint32_t ah[4][4];
#pragma unroll
            for (int mi = 0; mi < 4; mi++) {
                uint32_t aa = sbase + (arow + mi * 16) * ROW_B + acol * 2;
                asm volatile("ldmatrix.sync.aligned.m8n8.x4.shared.b16 {%0,%1,%2,%3}, [%4];"
                             : "=r"(ah[mi][0]), "=r"(ah[mi][1]), "=r"(ah[mi][2]), "=r"(ah[mi][3]) : "r"(aa));
            }
#pragma unroll
            for (int mi = 0; mi < 4; mi++)
#pragma unroll
                for (int ni = 0; ni < 4; ni++) mma16816h(acc[mi][ni], ah[mi], bh[ni]);
        }
    }

    __half* Pz = Pout + (size_t)z * MSZ;
    const int g = lane >> 2, tg = lane & 3;
#pragma unroll
    for (int mi = 0; mi < 4; mi++) {
        int row0 = by + wy * 64 + mi * 16 + g;
#pragma unroll
        for (int ni = 0; ni < 4; ni++) {
            int col = bx + wx * 32 + ni * 8 + tg * 2;
            float b0v = __ldg(bias + col), b1v = __ldg(bias + col + 1);
            *(uint32_t*)&Pz[(size_t)row0 * EMB + col] =
                pack_h2((acc[mi][ni][0] + b0v) * scale, (acc[mi][ni][1] + b1v) * scale);
            *(uint32_t*)&Pz[(size_t)(row0 + 8) * EMB + col] =
                pack_h2((acc[mi][ni][2] + b0v) * scale, (acc[mi][ni][3] + b1v) * scale);
        }
    }
}

// ---------------- O GEMM: A fp16 (context), W fp16, out fp32 ----------------
#define O_STAGE (2*TILE_BYT)
#define O_SMEM (2*O_STAGE)         // 40960

__global__ __launch_bounds__(256) void gemm_o(
    const __half* __restrict__ A, const __half* __restrict__ Whi,
    const float* __restrict__ bias, float* __restrict__ Cf)
{
    extern __shared__ char smc[];
    const int tid = threadIdx.x;
    const int lane = tid & 31, w = tid >> 5;
    const int wy = w >> 2, wx = w & 3;
    const int bx = blockIdx.x * 128, by = blockIdx.y * 128;
    const uint32_t sbase = smem_u32(smc);

    const char* gsrc[2] = {
        (const char*)(A   + (size_t)by * EMB),
        (const char*)(Whi + (size_t)bx * EMB)};

    auto prefetch = [&](int kb, int st) {
#pragma unroll
        for (int t = 0; t < 2; t++)
#pragma unroll
            for (int s = 0; s < 2; s++) {
                int idx = tid + s * 256;
                int r = idx >> 2, c = idx & 3;
                const char* src = gsrc[t] + ((size_t)r * EMB + (size_t)kb * BK) * 2 + c * 16;
                uint32_t dst = sbase + (uint32_t)st * O_STAGE + t * TILE_BYT
                             + (uint32_t)r * ROW_B + c * 16;
                asm volatile("cp.async.cg.shared.global [%0], [%1], 16;"
                             :: "r"(dst), "l"(src));
            }
        asm volatile("cp.async.commit_group;");
    };

    float acc[4][4][4];
#pragma unroll
    for (int mi = 0; mi < 4; mi++)
#pragma unroll
        for (int ni = 0; ni < 4; ni++)
#pragma unroll
            for (int j = 0; j < 4; j++) acc[mi][ni][j] = 0.f;

    prefetch(0, 0);

    for (int kb = 0; kb < NCHUNK; kb++) {
        asm volatile("cp.async.wait_group 0;");
        __syncthreads();
        if (kb + 1 < NCHUNK) prefetch(kb + 1, (kb + 1) & 1);
        const uint32_t st = sbase + (uint32_t)(kb & 1) * O_STAGE;

#pragma unroll
        for (int ks = 0; ks < 2; ks++) {
            uint32_t bh[4][2];
            const uint32_t brow = wx * 32 + (lane & 7);
            const uint32_t bcol = ks * 16 + ((lane >> 3) & 1) * 8;
#pragma unroll
            for (int ni = 0; ni < 4; ni++) {
                uint32_t ab = st + TILE_BYT + (brow + ni * 8) * ROW_B + bcol * 2;
                asm volatile("ldmatrix.sync.aligned.m8n8.x2.shared.b16 {%0,%1}, [%2];"
                             : "=r"(bh[ni][0]), "=r"(bh[ni][1]) : "r"(ab));
            }
            const uint32_t arow = wy * 64 + (lane & 15);
            const uint32_t acol = ks * 16 + (lane >> 4) * 8;
            uint32_t ah[4][4];
#pragma unroll
            for (int mi = 0; mi < 4; mi++) {
                uint32_t aa = st + (arow + mi * 16) * ROW_B + acol * 2;
                asm volatile("ldmatrix.sync.aligned.m8n8.x4.shared.b16 {%0,%1,%2,%3}, [%4];"
                             : "=r"(ah[mi][0]), "=r"(ah[mi][1]), "=r"(ah[mi][2]), "=r"(ah[mi][3]) : "r"(aa));
            }
#pragma unroll
            for (int mi = 0; mi < 4; mi++)
#pragma unroll
                for (int ni = 0; ni < 4; ni++) mma16816h(acc[mi][ni], ah[mi], bh[ni]);
        }
    }

    const int g = lane >> 2, tg = lane & 3;
#pragma unroll
    for (int mi = 0; mi < 4; mi++) {
        int row0 = by + wy * 64 + mi * 16 + g;
#pragma unroll
        for (int ni = 0; ni < 4; ni++) {
            int col = bx + wx * 32 + ni * 8 + tg * 2;
            float b0v = __ldg(bias + col), b1v = __ldg(bias + col + 1);
            float2 o0 = {acc[mi][ni][0] + b0v, acc[mi][ni][1] + b1v};
            float2 o1 = {acc[mi][ni][2] + b0v, acc[mi][ni][3] + b1v};
            *(float2*)&Cf[(size_t)row0 * EMB + col] = o0;
            *(float2*)&Cf[(size_t)(row0 + 8) * EMB + col] = o1;
        }
    }
}

// ---------------- fp16 flash attention (x4 K-fragment loads) ----------------
#define AT_ROW 144
#define AT_TILE (64*AT_ROW)
#define AT_STAGE (2*AT_TILE)
#define ATT_SMEM (2*AT_STAGE)      // 36864

__global__ __launch_bounds__(256) void attn_mma(
    const __half* __restrict__ Ph_, __half* __restrict__ Ch_)
{
    extern __shared__ char smc[];
    const uint32_t sbase = smem_u32(smc);
    const int tid = threadIdx.x, lane = tid & 31, w = tid >> 5;
    const int b = blockIdx.z, h = blockIdx.y;
    const int q0 = blockIdx.x * 128;
    const size_t base_e = ((size_t)b * SEQ) * EMB + h * HD;

    const __half* Qh_ = Ph_;
    const __half* Kh_ = Ph_ + MSZ;
    const __half* Vh_ = Ph_ + 2*MSZ;

#pragma unroll
    for (int s = 0; s < 4; s++) {
        int idx = tid + s * 256;
        int r = idx >> 3, c = idx & 7;
        const char* src = (const char*)(Qh_ + base_e + (size_t)(q0 + r) * EMB) + c * 16;
        uint32_t dst = sbase + (uint32_t)r * AT_ROW + c * 16;
        asm volatile("cp.async.cg.shared.global [%0], [%1], 16;" :: "r"(dst), "l"(src));
    }
    asm volatile("cp.async.commit_group;");
    asm volatile("cp.async.wait_group 0;");
    __syncthreads();

    uint32_t qh[4][4];
    {
        const uint32_t arow = w * 16 + (lane & 15);
#pragma unroll
        for (int ks = 0; ks < 4; ks++) {
            uint32_t aa = sbase + arow * AT_ROW + (ks * 16 + (lane >> 4) * 8) * 2;
            asm volatile("ldmatrix.sync.aligned.m8n8.x4.shared.b16 {%0,%1,%2,%3}, [%4];"
                : "=r"(qh[ks][0]), "=r"(qh[ks][1]), "=r"(qh[ks][2]), "=r"(qh[ks][3]) : "r"(aa));
        }
    }
    __syncthreads();

    const __half* kvsrc[2] = {Kh_, Vh_};
    auto prefetch = [&](int kb, int st) {
#pragma unroll
        for (int s = 0; s < 4; s++) {
            int idx = tid + s * 256;
            int t = idx >> 9, rem = idx & 511;
            int r = rem >> 3, c = rem & 7;
            const char* src = (const char*)(kvsrc[t] + base_e + (size_t)(kb * 64 + r) * EMB) + c * 16;
            uint32_t dst = sbase + (uint32_t)st * AT_STAGE + t * AT_TILE
                         + (uint32_t)r * AT_ROW + c * 16;
            asm volatile("cp.async.cg.shared.global [%0], [%1], 16;" :: "r"(dst), "l"(src));
        }
        asm volatile("cp.async.commit_group;");
    };

    float oacc[8][4];
    float m_i[2] = {-1e30f, -1e30f}, l_i[2] = {0.f, 0.f};
#pragma unroll
    for (int j = 0; j < 8; j++)
#pragma unroll
        for (int c = 0; c < 4; c++) oacc[j][c] = 0.f;

    prefetch(0, 0);

    for (int kb = 0; kb < SEQ/64; kb++) {
        asm volatile("cp.async.wait_group 0;");
        __syncthreads();
        if (kb + 1 < SEQ/64) prefetch(kb + 1, (kb + 1) & 1);
        const uint32_t st = sbase + (uint32_t)(kb & 1) * AT_STAGE;

        float sacc[8][4];
#pragma unroll
        for (int j = 0; j < 8; j++)
#pragma unroll
            for (int c = 0; c < 4; c++) sacc[j][c] = 0.f;

        // ---- S = Q K^T : x4 loads deliver B-frags for 2 adjacent j ----
        // lane mapping: row = j0*8 + (lane>>4)*8 + (lane&7),
        //               col = ks*16 + ((lane>>3)&1)*8
#pragma unroll
        for (int ks = 0; ks < 4; ks++) {
            const uint32_t bcol = ks * 16 + ((lane >> 3) & 1) * 8;
            const uint32_t brow8 = (lane >> 4) * 8 + (lane & 7);
#pragma unroll
            for (int jg = 0; jg < 2; jg++) {
                uint32_t bh[4][2];
#pragma unroll
                for (int jp = 0; jp < 2; jp++) {
                    int j0 = jg * 4 + jp * 2;
                    uint32_t ab = st + (j0 * 8 + brow8) * AT_ROW + bcol * 2;
                    uint32_t r0, r1, r2, r3;
                    asm volatile("ldmatrix.sync.aligned.m8n8.x4.shared.b16 {%0,%1,%2,%3}, [%4];"
                                 : "=r"(r0), "=r"(r1), "=r"(r2), "=r"(r3) : "r"(ab));
                    bh[jp*2][0] = r0;   bh[jp*2][1] = r1;
                    bh[jp*2+1][0] = r2; bh[jp*2+1][1] = r3;
                }
#pragma unroll
                for (int jj = 0; jj < 4; jj++) mma16816h(sacc[jg*4+jj], qh[ks], bh[jj]);
            }
        }

        // ---- online softmax ----
#pragma unroll
        for (int rh = 0; rh < 2; rh++) {
            float mx = -1e30f;
#pragma unroll
            for (int j = 0; j < 8; j++)
                mx = fmaxf(mx, fmaxf(sacc[j][2*rh], sacc[j][2*rh+1]));
            mx = fmaxf(mx, __shfl_xor_sync(0xffffffffu, mx, 1));
            mx = fmaxf(mx, __shfl_xor_sync(0xffffffffu, mx, 2));
            float m_new = fmaxf(m_i[rh], mx);
            float corr = __expf(m_i[rh] - m_new);
            float sum = 0.f;
#pragma unroll
            for (int j = 0; j < 8; j++) {
                float p0 = __expf(sacc[j][2*rh]   - m_new);
                float p1 = __expf(sacc[j][2*rh+1] - m_new);
                sacc[j][2*rh] = p0; sacc[j][2*rh+1] = p1;
                sum += p0 + p1;
            }
            sum += __shfl_xor_sync(0xffffffffu, sum, 1);
            sum += __shfl_xor_sync(0xffffffffu, sum, 2);
            l_i[rh] = l_i[rh] * corr + sum;
            m_i[rh] = m_new;
#pragma unroll
            for (int j = 0; j < 8; j++) {
                oacc[j][2*rh]   *= corr;
                oacc[j][2*rh+1] *= corr;
            }
        }

        uint32_t phi[4][4];
#pragma unroll
        for (int ks = 0; ks < 4; ks++) {
            phi[ks][0] = pack_h2(sacc[2*ks][0],   sacc[2*ks][1]);
            phi[ks][1] = pack_h2(sacc[2*ks][2],   sacc[2*ks][3]);
            phi[ks][2] = pack_h2(sacc[2*ks+1][0], sacc[2*ks+1][1]);
            phi[ks][3] = pack_h2(sacc[2*ks+1][2], sacc[2*ks+1][3]);
        }

#pragma unroll
        for (int ks = 0; ks < 4; ks++) {
            const uint32_t vrow = ks * 16 + (lane & 15);
            const uint32_t vsub = (lane >> 4) * 8;
#pragma unroll
            for (int jp = 0; jp < 2; jp++) {
                uint32_t vh0[4], vh1[4];
                uint32_t va = st + AT_TILE + vrow * AT_ROW + ((2*jp) * 16 + vsub) * 2;
                asm volatile("ldmatrix.sync.aligned.m8n8.x4.trans.shared.b16 {%0,%1,%2,%3}, [%4];"
                    : "=r"(vh0[0]), "=r"(vh0[1]), "=r"(vh0[2]), "=r"(vh0[3]) : "r"(va));
                uint32_t vb = va + 32;
                asm volatile("ldmatrix.sync.aligned.m8n8.x4.trans.shared.b16 {%0,%1,%2,%3}, [%4];"
                    : "=r"(vh1[0]), "=r"(vh1[1]), "=r"(vh1[2]), "=r"(vh1[3]) : "r"(vb));
                mma16816h(oacc[4*jp],   phi[ks], &vh0[0]);
                mma16816h(oacc[4*jp+1], phi[ks], &vh0[2]);
                mma16816h(oacc[4*jp+2], phi[ks], &vh1[0]);
                mma16816h(oacc[4*jp+3], phi[ks], &vh1[2]);
            }
        }
    }

    const int g = lane >> 2, tg = lane & 3;
#pragma unroll
    for (int rh = 0; rh < 2; rh++) {
        float inv = 1.0f / l_i[rh];
        int row = q0 + w * 16 + g + 8 * rh;
        size_t ro = base_e + (size_t)row * EMB;
#pragma unroll
        for (int j = 0; j < 8; j++) {
            int col = j * 8 + tg * 2;
            *(uint32_t*)&Ch_[ro + col] =
                pack_h2(oacc[j][2*rh] * inv, oacc[j][2*rh+1] * inv);
        }
    }
}

// ---------------------------------------------------------------------------
extern "C" void kernel_launch(void* const* d_in, const int* in_sizes, int n_in,
                              void* d_out, int out_size)
{
    const float* q  = (const float*)d_in[0];
    const float* k  = (const float*)d_in[1];
    const float* v  = (const float*)d_in[2];
    const float* Wq = (const float*)d_in[3];
    const float* bq = (const float*)d_in[4];
    const float* Wk = (const float*)d_in[5];
    const float* bk = (const float*)d_in[6];
    const float* Wv = (const float*)d_in[7];
    const float* bv = (const float*)d_in[8];
    const float* Wo = (const float*)d_in[9];
    const float* bo = (const float*)d_in[10];
    float* out = (float*)d_out;

    __half *wh, *ph, *ch;
    cudaGetSymbolAddress((void**)&wh, g_w_h);
    cudaGetSymbolAddress((void**)&ph, g_P_hi);
    cudaGetSymbolAddress((void**)&ch, g_Ch);

    cudaFuncSetAttribute(gemm_qkv,
        cudaFuncAttributeMaxDynamicSharedMemorySize, QKV_SMEM);
    cudaFuncSetAttribute(gemm_o,
        cudaFuncAttributeMaxDynamicSharedMemorySize, O_SMEM);
    cudaFuncSetAttribute(attn_mma,
        cudaFuncAttributeMaxDynamicSharedMemorySize, ATT_SMEM);

    SplitSrc ss;
    ss.p[0] = (const float4*)Wq; ss.p[1] = (const float4*)Wk;
    ss.p[2] = (const float4*)Wv; ss.p[3] = (const float4*)Wo;
    split_w<<<dim3((unsigned)(WSZ/4/256), 4), 256>>>(ss, (uint2*)wh);

    const float scaling = 0.125f;
    gemm_qkv<<<dim3(EMB/128, M_TOT/128, 3), 256, QKV_SMEM>>>(
        q, k, v, wh, bq, bk, bv, scaling, ph);

    attn_mma<<<dim3(SEQ/128, NH, BSZ), 256, ATT_SMEM>>>(ph, ch);

    gemm_o<<<dim3(EMB/128, M_TOT/128, 1), 256, O_SMEM>>>(
        ch, wh + 3*WSZ, bo, out);
}

// round 17
// speedup vs baseline: 1.5781x; 1.0222x over previous
#include <cuda_runtime.h>
#include <cuda_fp16.h>
#include <cstdint>
#include <math.h>

#define BSZ 8
#define SEQ 1024
#define EMB 1024
#define NH 16
#define HD 64
#define M_TOT (BSZ*SEQ)   // 8192
#define MSZ ((size_t)M_TOT*EMB)
#define WSZ ((size_t)EMB*EMB)

__device__ __half g_w_h[4*WSZ];     // weights (fp16)
__device__ __half g_P_hi[3*MSZ];    // projected Q/K/V (fp16)
__device__ __half g_Ch[MSZ];        // attention context (fp16)

__device__ __forceinline__ uint32_t smem_u32(const void* p) {
    uint32_t a;
    asm("{ .reg .u64 t; cvta.to.shared.u64 t, %1; cvt.u32.u64 %0, t; }"
        : "=r"(a) : "l"(p));
    return a;
}

__device__ __forceinline__ void mma16816h(float* c, const uint32_t* a, const uint32_t* b) {
    asm volatile(
        "mma.sync.aligned.m16n8k16.row.col.f32.f16.f16.f32 "
        "{%0,%1,%2,%3}, {%4,%5,%6,%7}, {%8,%9}, {%0,%1,%2,%3};"
        : "+f"(c[0]), "+f"(c[1]), "+f"(c[2]), "+f"(c[3])
        : "r"(a[0]), "r"(a[1]), "r"(a[2]), "r"(a[3]), "r"(b[0]), "r"(b[1]));
}

__device__ __forceinline__ uint32_t pack_h2(float x, float y) {
    __half2 p = {__float2half_rn(x), __float2half_rn(y)};
    return *reinterpret_cast<uint32_t*>(&p);
}

// ---------------- weight fp32 -> fp16 (4 tensors) ---------------------------
struct SplitSrc { const float4* p[4]; };

__global__ __launch_bounds__(256) void split_w(
    SplitSrc s, uint2* __restrict__ wh)
{
    const int seg = blockIdx.y;
    const int i = blockIdx.x * 256 + threadIdx.x;
    if (i >= (int)(WSZ/4)) return;
    float4 v = s.p[seg][i];
    uint2 ho;
    ho.x = pack_h2(v.x, v.y);
    ho.y = pack_h2(v.z, v.w);
    wh[(size_t)seg * (WSZ/4) + i] = ho;
}

// ---------------- QKV GEMM: A fp32 (fused convert), W fp16 ------------------
// A double-buffered (1 barrier/chunk); x4 W-fragment loads.
#define BK 32
#define NCHUNK (EMB/BK)
#define ROW_B 80
#define TILE_BYT (128*ROW_B)       // 10240
#define QKV_SMEM (4*TILE_BYT)      // A x2 + Wh x2 stages = 40960

__global__ __launch_bounds__(256) void gemm_qkv(
    const float* __restrict__ in_q, const float* __restrict__ in_k,
    const float* __restrict__ in_v,
    const __half* __restrict__ Wbase_h,
    const float* __restrict__ b0, const float* __restrict__ b1,
    const float* __restrict__ b2, float scale0,
    __half* __restrict__ Pout)
{
    extern __shared__ char smc[];
    const int z = blockIdx.z;
    const int tid = threadIdx.x;
    const int lane = tid & 31, w = tid >> 5;
    const int wy = w >> 2, wx = w & 3;
    const int bx = blockIdx.x * 128, by = blockIdx.y * 128;
    const uint32_t sbase = smem_u32(smc);

    const float* A = (z == 0) ? in_q : ((z == 1) ? in_k : in_v);
    const float* Asrc = A + (size_t)by * EMB;
    const __half* Whi = Wbase_h + (size_t)z * WSZ;
    const float* bias = (z == 0) ? b0 : ((z == 1) ? b1 : b2);
    const float scale = (z == 0) ? scale0 : 1.0f;

    const char* wsrc = (const char*)(Whi + (size_t)bx * EMB);

    auto prefetchW = [&](int kb, int st) {
#pragma unroll
        for (int s = 0; s < 2; s++) {
            int idx = tid + s * 256;
            int r = idx >> 2, c = idx & 3;
            const char* src = wsrc + ((size_t)r * EMB + (size_t)kb * BK) * 2 + c * 16;
            uint32_t dst = sbase + 2*TILE_BYT + (uint32_t)st * TILE_BYT
                         + (uint32_t)r * ROW_B + c * 16;
            asm volatile("cp.async.cg.shared.global [%0], [%1], 16;"
                         :: "r"(dst), "l"(src));
        }
        asm volatile("cp.async.commit_group;");
    };

    float4 rA[2][2];
    auto ldgA = [&](int kb) {
#pragma unroll
        for (int s = 0; s < 2; s++) {
            int idx = tid + s * 256;
            int r = idx >> 2, c = idx & 3;
            const float* p = Asrc + (size_t)r * EMB + kb * BK + c * 8;
            rA[s][0] = *(const float4*)p;
            rA[s][1] = *(const float4*)(p + 4);
        }
    };
    auto stsA = [&](int buf) {
#pragma unroll
        for (int s = 0; s < 2; s++) {
            int idx = tid + s * 256;
            int r = idx >> 2, c = idx & 3;
            uint4 val;
            val.x = pack_h2(rA[s][0].x, rA[s][0].y);
            val.y = pack_h2(rA[s][0].z, rA[s][0].w);
            val.z = pack_h2(rA[s][1].x, rA[s][1].y);
            val.w = pack_h2(rA[s][1].z, rA[s][1].w);
            *(uint4*)(smc + (uint32_t)buf * TILE_BYT + (uint32_t)r * ROW_B + c * 16) = val;
        }
    };

    float acc[4][4][4];
#pragma unroll
    for (int mi = 0; mi < 4; mi++)
#pragma unroll
        for (int ni = 0; ni < 4; ni++)
#pragma unroll
            for (int j = 0; j < 4; j++) acc[mi][ni][j] = 0.f;

    prefetchW(0, 0);
    ldgA(0);

    const uint32_t wrow8 = (lane >> 4) * 8 + (lane & 7);
    const uint32_t wcsel = ((lane >> 3) & 1) * 8;

    for (int kb = 0; kb < NCHUNK; kb++) {
        asm volatile("cp.async.wait_group 0;");
        stsA(kb & 1);             // A(kb) -> buffer kb&1 (disjoint from kb-1's)
        __syncthreads();          // publishes A(kb) + W(kb); fences compute(kb-1)
        if (kb + 1 < NCHUNK) { prefetchW(kb + 1, (kb + 1) & 1); ldgA(kb + 1); }
        const uint32_t ab_ = sbase + (uint32_t)(kb & 1) * TILE_BYT;
        const uint32_t wb = sbase + 2*TILE_BYT + (uint32_t)(kb & 1) * TILE_BYT;

#pragma unroll
        for (int ks = 0; ks < 2; ks++) {
            uint32_t bh[4][2];
            const uint32_t bcol = ks * 16 + wcsel;
#pragma unroll
            for (int jp = 0; jp < 2; jp++) {   // x4: two adjacent ni per load
                uint32_t ab2 = wb + (wx * 32 + jp * 16 + wrow8) * ROW_B + bcol * 2;
                uint32_t r0, r1, r2, r3;
                asm volatile("ldmatrix.sync.aligned.m8n8.x4.shared.b16 {%0,%1,%2,%3}, [%4];"
                             : "=r"(r0), "=r"(r1), "=r"(r2), "=r"(r3) : "r"(ab2));
                bh[jp*2][0] = r0;   bh[jp*2][1] = r1;
                bh[jp*2+1][0] = r2; bh[jp*2+1][1] = r3;
            }
            const uint32_t arow = wy * 64 + (lane & 15);
            const uint32_t acol = ks * 16 + (lane >> 4) * 8;
            uint32_t ah[4][4];
#pragma unroll
            for (int mi = 0; mi < 4; mi++) {
                uint32_t aa = ab_ + (arow + mi * 16) * ROW_B + acol * 2;
                asm volatile("ldmatrix.sync.aligned.m8n8.x4.shared.b16 {%0,%1,%2,%3}, [%4];"
                             : "=r"(ah[mi][0]), "=r"(ah[mi][1]), "=r"(ah[mi][2]), "=r"(ah[mi][3]) : "r"(aa));
            }
#pragma unroll
            for (int mi = 0; mi < 4; mi++)
#pragma unroll
                for (int ni = 0; ni < 4; ni++) mma16816h(acc[mi][ni], ah[mi], bh[ni]);
        }
    }

    __half* Pz = Pout + (size_t)z * MSZ;
    const int g = lane >> 2, tg = lane & 3;
#pragma unroll
    for (int mi = 0; mi < 4; mi++) {
        int row0 = by + wy * 64 + mi * 16 + g;
#pragma unroll
        for (int ni = 0; ni < 4; ni++) {
            int col = bx + wx * 32 + ni * 8 + tg * 2;
            float b0v = __ldg(bias + col), b1v = __ldg(bias + col + 1);
            *(uint32_t*)&Pz[(size_t)row0 * EMB + col] =
                pack_h2((acc[mi][ni][0] + b0v) * scale, (acc[mi][ni][1] + b1v) * scale);
            *(uint32_t*)&Pz[(size_t)(row0 + 8) * EMB + col] =
                pack_h2((acc[mi][ni][2] + b0v) * scale, (acc[mi][ni][3] + b1v) * scale);
        }
    }
}

// ---------------- O GEMM: A fp16 (context), W fp16, out fp32 ----------------
#define O_STAGE (2*TILE_BYT)
#define O_SMEM (2*O_STAGE)         // 40960

__global__ __launch_bounds__(256) void gemm_o(
    const __half* __restrict__ A, const __half* __restrict__ Whi,
    const float* __restrict__ bias, float* __restrict__ Cf)
{
    extern __shared__ char smc[];
    const int tid = threadIdx.x;
    const int lane = tid & 31, w = tid >> 5;
    const int wy = w >> 2, wx = w & 3;
    const int bx = blockIdx.x * 128, by = blockIdx.y * 128;
    const uint32_t sbase = smem_u32(smc);

    const char* gsrc[2] = {
        (const char*)(A   + (size_t)by * EMB),
        (const char*)(Whi + (size_t)bx * EMB)};

    auto prefetch = [&](int kb, int st) {
#pragma unroll
        for (int t = 0; t < 2; t++)
#pragma unroll
            for (int s = 0; s < 2; s++) {
                int idx = tid + s * 256;
                int r = idx >> 2, c = idx & 3;
                const char* src = gsrc[t] + ((size_t)r * EMB + (size_t)kb * BK) * 2 + c * 16;
                uint32_t dst = sbase + (uint32_t)st * O_STAGE + t * TILE_BYT
                             + (uint32_t)r * ROW_B + c * 16;
                asm volatile("cp.async.cg.shared.global [%0], [%1], 16;"
                             :: "r"(dst), "l"(src));
            }
        asm volatile("cp.async.commit_group;");
    };

    float acc[4][4][4];
#pragma unroll
    for (int mi = 0; mi < 4; mi++)
#pragma unroll
        for (int ni = 0; ni < 4; ni++)
#pragma unroll
            for (int j = 0; j < 4; j++) acc[mi][ni][j] = 0.f;

    prefetch(0, 0);

    const uint32_t wrow8 = (lane >> 4) * 8 + (lane & 7);
    const uint32_t wcsel = ((lane >> 3) & 1) * 8;

    for (int kb = 0; kb < NCHUNK; kb++) {
        asm volatile("cp.async.wait_group 0;");
        __syncthreads();
        if (kb + 1 < NCHUNK) prefetch(kb + 1, (kb + 1) & 1);
        const uint32_t st = sbase + (uint32_t)(kb & 1) * O_STAGE;

#pragma unroll
        for (int ks = 0; ks < 2; ks++) {
            uint32_t bh[4][2];
            const uint32_t bcol = ks * 16 + wcsel;
#pragma unroll
            for (int jp = 0; jp < 2; jp++) {
                uint32_t ab2 = st + TILE_BYT + (wx * 32 + jp * 16 + wrow8) * ROW_B + bcol * 2;
                uint32_t r0, r1, r2, r3;
                asm volatile("ldmatrix.sync.aligned.m8n8.x4.shared.b16 {%0,%1,%2,%3}, [%4];"
                             : "=r"(r0), "=r"(r1), "=r"(r2), "=r"(r3) : "r"(ab2));
                bh[jp*2][0] = r0;   bh[jp*2][1] = r1;
                bh[jp*2+1][0] = r2; bh[jp*2+1][1] = r3;
            }
            const uint32_t arow = wy * 64 + (lane & 15);
            const uint32_t acol = ks * 16 + (lane >> 4) * 8;
            uint32_t ah[4][4];
#pragma unroll
            for (int mi = 0; mi < 4; mi++) {
                uint32_t aa = st + (arow + mi * 16) * ROW_B + acol * 2;
                asm volatile("ldmatrix.sync.aligned.m8n8.x4.shared.b16 {%0,%1,%2,%3}, [%4];"
                             : "=r"(ah[mi][0]), "=r"(ah[mi][1]), "=r"(ah[mi][2]), "=r"(ah[mi][3]) : "r"(aa));
            }
#pragma unroll
            for (int mi = 0; mi < 4; mi++)
#pragma unroll
                for (int ni = 0; ni < 4; ni++) mma16816h(acc[mi][ni], ah[mi], bh[ni]);
        }
    }

    const int g = lane >> 2, tg = lane & 3;
#pragma unroll
    for (int mi = 0; mi < 4; mi++) {
        int row0 = by + wy * 64 + mi * 16 + g;
#pragma unroll
        for (int ni = 0; ni < 4; ni++) {
            int col = bx + wx * 32 + ni * 8 + tg * 2;
            float b0v = __ldg(bias + col), b1v = __ldg(bias + col + 1);
            float2 o0 = {acc[mi][ni][0] + b0v, acc[mi][ni][1] + b1v};
            float2 o1 = {acc[mi][ni][2] + b0v, acc[mi][ni][3] + b1v};
            *(float2*)&Cf[(size_t)row0 * EMB + col] = o0;
            *(float2*)&Cf[(size_t)(row0 + 8) * EMB + col] = o1;
        }
    }
}

// ---------------- fp16 flash attention (R16 verbatim) -----------------------
#define AT_ROW 144
#define AT_TILE (64*AT_ROW)
#define AT_STAGE (2*AT_TILE)
#define ATT_SMEM (2*AT_STAGE)      // 36864

__global__ __launch_bounds__(256) void attn_mma(
    const __half* __restrict__ Ph_, __half* __restrict__ Ch_)
{
    extern __shared__ char smc[];
    const uint32_t sbase = smem_u32(smc);
    const int tid = threadIdx.x, lane = tid & 31, w = tid >> 5;
    const int b = blockIdx.z, h = blockIdx.y;
    const int q0 = blockIdx.x * 128;
    const size_t base_e = ((size_t)b * SEQ) * EMB + h * HD;

    const __half* Qh_ = Ph_;
    const __half* Kh_ = Ph_ + MSZ;
    const __half* Vh_ = Ph_ + 2*MSZ;

#pragma unroll
    for (int s = 0; s < 4; s++) {
        int idx = tid + s * 256;
        int r = idx >> 3, c = idx & 7;
        const char* src = (const char*)(Qh_ + base_e + (size_t)(q0 + r) * EMB) + c * 16;
        uint32_t dst = sbase + (uint32_t)r * AT_ROW + c * 16;
        asm volatile("cp.async.cg.shared.global [%0], [%1], 16;" :: "r"(dst), "l"(src));
    }
    asm volatile("cp.async.commit_group;");
    asm volatile("cp.async.wait_group 0;");
    __syncthreads();

    uint32_t qh[4][4];
    {
        const uint32_t arow = w * 16 + (lane & 15);
#pragma unroll
        for (int ks = 0; ks < 4; ks++) {
            uint32_t aa = sbase + arow * AT_ROW + (ks * 16 + (lane >> 4) * 8) * 2;
            asm volatile("ldmatrix.sync.aligned.m8n8.x4.shared.b16 {%0,%1,%2,%3}, [%4];"
                : "=r"(qh[ks][0]), "=r"(qh[ks][1]), "=r"(qh[ks][2]), "=r"(qh[ks][3]) : "r"(aa));
        }
    }
    __syncthreads();

    const __half* kvsrc[2] = {Kh_, Vh_};
    auto prefetch = [&](int kb, int st) {
#pragma unroll
        for (int s = 0; s < 4; s++) {
            int idx = tid + s * 256;
            int t = idx >> 9, rem = idx & 511;
            int r = rem >> 3, c = rem & 7;
            const char* src = (const char*)(kvsrc[t] + base_e + (size_t)(kb * 64 + r) * EMB) + c * 16;
            uint32_t dst = sbase + (uint32_t)st * AT_STAGE + t * AT_TILE
                         + (uint32_t)r * AT_ROW + c * 16;
            asm volatile("cp.async.cg.shared.global [%0], [%1], 16;" :: "r"(dst), "l"(src));
        }
        asm volatile("cp.async.commit_group;");
    };

    float oacc[8][4];
    float m_i[2] = {-1e30f, -1e30f}, l_i[2] = {0.f, 0.f};
#pragma unroll
    for (int j = 0; j < 8; j++)
#pragma unroll
        for (int c = 0; c < 4; c++) oacc[j][c] = 0.f;

    prefetch(0, 0);

    for (int kb = 0; kb < SEQ/64; kb++) {
        asm volatile("cp.async.wait_group 0;");
        __syncthreads();
        if (kb + 1 < SEQ/64) prefetch(kb + 1, (kb + 1) & 1);
        const uint32_t st = sbase + (uint32_t)(kb & 1) * AT_STAGE;

        float sacc[8][4];
#pragma unroll
        for (int j = 0; j < 8; j++)
#pragma unroll
            for (int c = 0; c < 4; c++) sacc[j][c] = 0.f;

#pragma unroll
        for (int ks = 0; ks < 4; ks++) {
            const uint32_t bcol = ks * 16 + ((lane >> 3) & 1) * 8;
            const uint32_t brow8 = (lane >> 4) * 8 + (lane & 7);
#pragma unroll
            for (int jg = 0; jg < 2; jg++) {
                uint32_t bh[4][2];
#pragma unroll
                for (int jp = 0; jp < 2; jp++) {
                    int j0 = jg * 4 + jp * 2;
                    uint32_t ab = st + (j0 * 8 + brow8) * AT_ROW + bcol * 2;
                    uint32_t r0, r1, r2, r3;
                    asm volatile("ldmatrix.sync.aligned.m8n8.x4.shared.b16 {%0,%1,%2,%3}, [%4];"
                                 : "=r"(r0), "=r"(r1), "=r"(r2), "=r"(r3) : "r"(ab));
                    bh[jp*2][0] = r0;   bh[jp*2][1] = r1;
                    bh[jp*2+1][0] = r2; bh[jp*2+1][1] = r3;
                }
#pragma unroll
                for (int jj = 0; jj < 4; jj++) mma16816h(sacc[jg*4+jj], qh[ks], bh[jj]);
            }
        }

#pragma unroll
        for (int rh = 0; rh < 2; rh++) {
            float mx = -1e30f;
#pragma unroll
            for (int j = 0; j < 8; j++)
                mx = fmaxf(mx, fmaxf(sacc[j][2*rh], sacc[j][2*rh+1]));
            mx = fmaxf(mx, __shfl_xor_sync(0xffffffffu, mx, 1));
            mx = fmaxf(mx, __shfl_xor_sync(0xffffffffu, mx, 2));
            float m_new = fmaxf(m_i[rh], mx);
            float corr = __expf(m_i[rh] - m_new);
            float sum = 0.f;
#pragma unroll
            for (int j = 0; j < 8; j++) {
                float p0 = __expf(sacc[j][2*rh]   - m_new);
                float p1 = __expf(sacc[j][2*rh+1] - m_new);
                sacc[j][2*rh] = p0; sacc[j][2*rh+1] = p1;
                sum += p0 + p1;
            }
            sum += __shfl_xor_sync(0xffffffffu, sum, 1);
            sum += __shfl_xor_sync(0xffffffffu, sum, 2);
            l_i[rh] = l_i[rh] * corr + sum;
            m_i[rh] = m_new;
#pragma unroll
            for (int j = 0; j < 8; j++) {
                oacc[j][2*rh]   *= corr;
                oacc[j][2*rh+1] *= corr;
            }
        }

        uint32_t phi[4][4];
#pragma unroll
        for (int ks = 0; ks < 4; ks++) {
            phi[ks][0] = pack_h2(sacc[2*ks][0],   sacc[2*ks][1]);
            phi[ks][1] = pack_h2(sacc[2*ks][2],   sacc[2*ks][3]);
            phi[ks][2] = pack_h2(sacc[2*ks+1][0], sacc[2*ks+1][1]);
            phi[ks][3] = pack_h2(sacc[2*ks+1][2], sacc[2*ks+1][3]);
        }

#pragma unroll
        for (int ks = 0; ks < 4; ks++) {
            const uint32_t vrow = ks * 16 + (lane & 15);
            const uint32_t vsub = (lane >> 4) * 8;
#pragma unroll
            for (int jp = 0; jp < 2; jp++) {
                uint32_t vh0[4], vh1[4];
                uint32_t va = st + AT_TILE + vrow * AT_ROW + ((2*jp) * 16 + vsub) * 2;
                asm volatile("ldmatrix.sync.aligned.m8n8.x4.trans.shared.b16 {%0,%1,%2,%3}, [%4];"
                    : "=r"(vh0[0]), "=r"(vh0[1]), "=r"(vh0[2]), "=r"(vh0[3]) : "r"(va));
                uint32_t vb = va + 32;
                asm volatile("ldmatrix.sync.aligned.m8n8.x4.trans.shared.b16 {%0,%1,%2,%3}, [%4];"
                    : "=r"(vh1[0]), "=r"(vh1[1]), "=r"(vh1[2]), "=r"(vh1[3]) : "r"(vb));
                mma16816h(oacc[4*jp],   phi[ks], &vh0[0]);
                mma16816h(oacc[4*jp+1], phi[ks], &vh0[2]);
                mma16816h(oacc[4*jp+2], phi[ks], &vh1[0]);
                mma16816h(oacc[4*jp+3], phi[ks], &vh1[2]);
            }
        }
    }

    const int g = lane >> 2, tg = lane & 3;
#pragma unroll
    for (int rh = 0; rh < 2; rh++) {
        float inv = 1.0f / l_i[rh];
        int row = q0 + w * 16 + g + 8 * rh;
        size_t ro = base_e + (size_t)row * EMB;
#pragma unroll
        for (int j = 0; j < 8; j++) {
            int col = j * 8 + tg * 2;
            *(uint32_t*)&Ch_[ro + col] =
                pack_h2(oacc[j][2*rh] * inv, oacc[j][2*rh+1] * inv);
        }
    }
}

// ---------------------------------------------------------------------------
extern "C" void kernel_launch(void* const* d_in, const int* in_sizes, int n_in,
                              void* d_out, int out_size)
{
    const float* q  = (const float*)d_in[0];
    const float* k  = (const float*)d_in[1];
    const float* v  = (const float*)d_in[2];
    const float* Wq = (const float*)d_in[3];
    const float* bq = (const float*)d_in[4];
    const float* Wk = (const float*)d_in[5];
    const float* bk = (const float*)d_in[6];
    const float* Wv = (const float*)d_in[7];
    const float* bv = (const float*)d_in[8];
    const float* Wo = (const float*)d_in[9];
    const float* bo = (const float*)d_in[10];
    float* out = (float*)d_out;

    __half *wh, *ph, *ch;
    cudaGetSymbolAddress((void**)&wh, g_w_h);
    cudaGetSymbolAddress((void**)&ph, g_P_hi);
    cudaGetSymbolAddress((void**)&ch, g_Ch);

    cudaFuncSetAttribute(gemm_qkv,
        cudaFuncAttributeMaxDynamicSharedMemorySize, QKV_SMEM);
    cudaFuncSetAttribute(gemm_o,
        cudaFuncAttributeMaxDynamicSharedMemorySize, O_SMEM);
    cudaFuncSetAttribute(attn_mma,
        cudaFuncAttributeMaxDynamicSharedMemorySize, ATT_SMEM);

    SplitSrc ss;
    ss.p[0] = (const float4*)Wq; ss.p[1] = (const float4*)Wk;
    ss.p[2] = (const float4*)Wv; ss.p[3] = (const float4*)Wo;
    split_w<<<dim3((unsigned)(WSZ/4/256), 4), 256>>>(ss, (uint2*)wh);

    const float scaling = 0.125f;
    gemm_qkv<<<dim3(EMB/128, M_TOT/128, 3), 256, QKV_SMEM>>>(
        q, k, v, wh, bq, bk, bv, scaling, ph);

    attn_mma<<<dim3(SEQ/128, NH, BSZ), 256, ATT_SMEM>>>(ph, ch);

    gemm_o<<<dim3(EMB/128, M_TOT/128, 1), 256, O_SMEM>>>(
        ch, wh + 3*WSZ, bo, out);
}